// round 15
// baseline (speedup 1.0000x reference)
#include <cuda_runtime.h>
#include <cuda_fp16.h>
#include <cstdint>
#include <math.h>

#define S_LEN   4096
#define DMODEL  2048
#define NH      16
#define NKV     4
#define HD      128
#define KV_DIM  (NKV * HD)        // 512
#define NQKV    (DMODEL + 2 * KV_DIM)   // 3072

// ---------------- device scratch (allocation-free rule) ----------------
__device__ __half g_Xhi[S_LEN * DMODEL];
__device__ __half g_Xlo[S_LEN * DMODEL];
__device__ __half g_Qhi[S_LEN * DMODEL];
__device__ __half g_Qlo[S_LEN * DMODEL];
__device__ __half g_Kh[S_LEN * KV_DIM];
__device__ __half g_Vh[S_LEN * KV_DIM];
__device__ __half g_Ohi[S_LEN * DMODEL];
__device__ __half g_Olo[S_LEN * DMODEL];
__device__ __half g_WqkvT[NQKV * DMODEL];
__device__ __half g_WoT[DMODEL * DMODEL];

// ---------------- PTX helpers (compute_103-safe: sm_80-era ISA) ----------------
__device__ __forceinline__ uint32_t smem_u32(const void* p) {
    uint32_t a;
    asm("{ .reg .u64 t; cvta.to.shared.u64 t, %1; cvt.u32.u64 %0, t; }"
        : "=r"(a) : "l"(p));
    return a;
}
__device__ __forceinline__ void cp_async16(uint32_t dst, const void* src) {
    asm volatile("cp.async.cg.shared.global [%0], [%1], 16;" :: "r"(dst), "l"(src));
}
#define CP_COMMIT() asm volatile("cp.async.commit_group;" ::: "memory")
#define CP_WAIT(n)  asm volatile("cp.async.wait_group %0;" :: "n"(n) : "memory")

__device__ __forceinline__ void ldm_x4(uint32_t& r0, uint32_t& r1, uint32_t& r2,
                                       uint32_t& r3, uint32_t addr) {
    asm volatile("ldmatrix.sync.aligned.m8n8.x4.shared.b16 {%0,%1,%2,%3}, [%4];"
                 : "=r"(r0), "=r"(r1), "=r"(r2), "=r"(r3) : "r"(addr));
}
__device__ __forceinline__ void ldm_x4_t(uint32_t& r0, uint32_t& r1, uint32_t& r2,
                                         uint32_t& r3, uint32_t addr) {
    asm volatile("ldmatrix.sync.aligned.m8n8.x4.trans.shared.b16 {%0,%1,%2,%3}, [%4];"
                 : "=r"(r0), "=r"(r1), "=r"(r2), "=r"(r3) : "r"(addr));
}
__device__ __forceinline__ void mma_f16(float& d0, float& d1, float& d2, float& d3,
                                        uint32_t a0, uint32_t a1, uint32_t a2,
                                        uint32_t a3, uint32_t b0, uint32_t b1) {
    asm volatile(
        "mma.sync.aligned.m16n8k16.row.col.f32.f16.f16.f32 "
        "{%0,%1,%2,%3}, {%4,%5,%6,%7}, {%8,%9}, {%0,%1,%2,%3};"
        : "+f"(d0), "+f"(d1), "+f"(d2), "+f"(d3)
        : "r"(a0), "r"(a1), "r"(a2), "r"(a3), "r"(b0), "r"(b1));
}
__device__ __forceinline__ uint32_t pack_hi(float x, float y, float& rx, float& ry) {
    __half hx = __float2half(x), hy = __float2half(y);
    rx = x - __half2float(hx);
    ry = y - __half2float(hy);
    __half2 p = __halves2half2(hx, hy);
    return *(uint32_t*)&p;
}
__device__ __forceinline__ uint32_t pack_h(float x, float y) {
    __half2 p = __halves2half2(__float2half(x), __float2half(y));
    return *(uint32_t*)&p;
}
__device__ __forceinline__ uint32_t swz64(uint32_t o) {
    return o ^ ((o >> 3) & 0x30);
}

// ---------------------------------------------------------------------------
__global__ void split_rm(const float* __restrict__ src,
                         __half* __restrict__ hi,
                         __half* __restrict__ lo, int n)
{
    int i = blockIdx.x * blockDim.x + threadIdx.x;
    if (i >= n) return;
    float f = src[i];
    __half h = __float2half(f);
    hi[i] = h;
    lo[i] = __float2half(f - __half2float(h));
}

// ---------------------------------------------------------------------------
__global__ __launch_bounds__(256) void split_tr3(const float* __restrict__ Wq,
                                                 const float* __restrict__ Wk,
                                                 const float* __restrict__ Wv,
                                                 __half* __restrict__ hT)
{
    const int bx = blockIdx.x;
    const float* W; int N, n0, dro;
    if (bx < 64)      { W = Wq; N = DMODEL; n0 = bx * 32;        dro = 0; }
    else if (bx < 80) { W = Wk; N = KV_DIM; n0 = (bx - 64) * 32; dro = DMODEL; }
    else              { W = Wv; N = KV_DIM; n0 = (bx - 80) * 32; dro = DMODEL + KV_DIM; }

    __shared__ float s[32][33];
    int k0 = blockIdx.y * 32;
    int tx = threadIdx.x & 31, ty = threadIdx.x >> 5;
    #pragma unroll
    for (int j = 0; j < 4; j++)
        s[ty + j * 8][tx] = W[(size_t)(k0 + ty + j * 8) * N + n0 + tx];
    __syncthreads();
    #pragma unroll
    for (int j = 0; j < 4; j++) {
        int nn = ty + j * 8;
        hT[(size_t)(dro + n0 + nn) * DMODEL + k0 + tx] = __float2half(s[tx][nn]);
    }
}

// ---------------------------------------------------------------------------
__global__ __launch_bounds__(256) void split_tr(const float* __restrict__ W,
                                                __half* __restrict__ hT,
                                                int K, int N)
{
    __shared__ float s[32][33];
    int n0 = blockIdx.x * 32, k0 = blockIdx.y * 32;
    int tx = threadIdx.x & 31, ty = threadIdx.x >> 5;
    #pragma unroll
    for (int j = 0; j < 4; j++)
        s[ty + j * 8][tx] = W[(size_t)(k0 + ty + j * 8) * N + n0 + tx];
    __syncthreads();
    #pragma unroll
    for (int j = 0; j < 4; j++) {
        int nn = ty + j * 8;
        hT[(size_t)(n0 + nn) * K + k0 + tx] = __float2half(s[tx][nn]);
    }
}

// ---------------------------------------------------------------------------
// mma.sync fp16x2 GEMM: C = (Ahi+Alo) @ (B[N,K])^T.
// CTA 128x128, BK=32, 8 warps, 3-stage cp.async pipeline, 2 CTA/SM.
// mode 0: fp32 C.   mode 1: fused RoPE+split epilogue (QKV: each 128-col
//         tile is one head; writes g_Qhi/Qlo, g_Kh, g_Vh directly).
// ---------------------------------------------------------------------------
#define GS_TILE   8192
#define GS_STAGE  24576
#define GEMM_SMEM 73728   // >= 128*132*4 = 67584 needed by mode-1 epilogue

__global__ __launch_bounds__(256, 2) void gemm_mma(
    const __half* __restrict__ Ahi, const __half* __restrict__ Alo,
    const __half* __restrict__ B,
    float* __restrict__ C,
    const float* __restrict__ cosp, const float* __restrict__ sinp,
    int M, int N, int K, int mode)
{
    extern __shared__ char dsm[];
    const uint32_t sbase = smem_u32(dsm);

    const int tid  = threadIdx.x;
    const int lane = tid & 31;
    const int w    = tid >> 5;
    const int wm   = w >> 2;
    const int wn   = w & 3;
    const int n0 = blockIdx.x * 128, m0 = blockIdx.y * 128;

    const __half* srcs[3] = {
        Ahi + (size_t)m0 * K, Alo + (size_t)m0 * K, B + (size_t)n0 * K };

    auto load_stage = [&](int stg, int kk) {
        uint32_t sb = sbase + stg * GS_STAGE;
        #pragma unroll
        for (int it = 0; it < 6; it++) {
            int idx  = it * 256 + tid;
            int tile = idx / 512;
            int rem  = idx & 511;
            int r    = rem >> 2;
            int c    = rem & 3;
            cp_async16(sb + tile * GS_TILE + swz64(r * 64 + c * 16),
                       srcs[tile] + (size_t)r * K + kk + c * 8);
        }
        CP_COMMIT();
    };

    float acc[4][4][4];
    #pragma unroll
    for (int i = 0; i < 4; i++)
        #pragma unroll
        for (int j = 0; j < 4; j++)
            #pragma unroll
            for (int q = 0; q < 4; q++) acc[i][j][q] = 0.f;

    const int ns = K >> 5;
    load_stage(0, 0);
    load_stage(1, 32);

    const uint32_t ldr = (lane & 15);
    const uint32_t ldc = (lane >> 4) * 16;

    for (int i = 0; i < ns; i++) {
        if (i + 1 < ns) { CP_WAIT(1); }
        else            { CP_WAIT(0); }
        __syncthreads();
        if (i + 2 < ns) load_stage((i + 2) % 3, (i + 2) * 32);

        const uint32_t sA = sbase + (i % 3) * GS_STAGE;
        const uint32_t sB = sA + 2 * GS_TILE;

        #pragma unroll
        for (int ks = 0; ks < 2; ks++) {
            const uint32_t kboff = ks * 32 + ldc;
            uint32_t af[2][4][4];
            #pragma unroll
            for (int p = 0; p < 2; p++)
                #pragma unroll
                for (int mt = 0; mt < 4; mt++)
                    ldm_x4(af[p][mt][0], af[p][mt][1], af[p][mt][2], af[p][mt][3],
                           sA + p * GS_TILE +
                           swz64((wm * 64 + mt * 16 + ldr) * 64 + kboff));

            #pragma unroll
            for (int nh = 0; nh < 2; nh++) {
                uint32_t bfr[4];
                ldm_x4(bfr[0], bfr[1], bfr[2], bfr[3],
                       sB + swz64((wn * 32 + nh * 16 + ldr) * 64 + kboff));

                #pragma unroll
                for (int mt = 0; mt < 4; mt++)
                    #pragma unroll
                    for (int sub = 0; sub < 2; sub++) {
                        float* d = acc[mt][nh * 2 + sub];
                        mma_f16(d[0], d[1], d[2], d[3],
                                af[0][mt][0], af[0][mt][1], af[0][mt][2], af[0][mt][3],
                                bfr[sub], bfr[sub + 2]);
                    }
                #pragma unroll
                for (int mt = 0; mt < 4; mt++)
                    #pragma unroll
                    for (int sub = 0; sub < 2; sub++) {
                        float* d = acc[mt][nh * 2 + sub];
                        mma_f16(d[0], d[1], d[2], d[3],
                                af[1][mt][0], af[1][mt][1], af[1][mt][2], af[1][mt][3],
                                bfr[sub], bfr[sub + 2]);
                    }
            }
        }
    }

    const int trow = lane >> 2;
    const int tcol = (lane & 3) * 2;

    if (mode == 0) {
        #pragma unroll
        for (int mt = 0; mt < 4; mt++)
            #pragma unroll
            for (int nt = 0; nt < 4; nt++) {
                const int rr = m0 + wm * 64 + mt * 16 + trow;
                const int cc = n0 + wn * 32 + nt * 8 + tcol;
                *(float2*)&C[(size_t)rr * N + cc] =
                    make_float2(acc[mt][nt][0], acc[mt][nt][1]);
                *(float2*)&C[(size_t)(rr + 8) * N + cc] =
                    make_float2(acc[mt][nt][2], acc[mt][nt][3]);
            }
        return;
    }

    // ---- mode 1: fused RoPE + fp16-split epilogue via smem ----
    __syncthreads();              // pipeline buffers no longer needed
    float* smf = (float*)dsm;     // 128 x 132 fp32 tile
    #pragma unroll
    for (int mt = 0; mt < 4; mt++)
        #pragma unroll
        for (int nt = 0; nt < 4; nt++) {
            const int rl = wm * 64 + mt * 16 + trow;
            const int cl = wn * 32 + nt * 8 + tcol;
            smf[rl * 132 + cl]     = acc[mt][nt][0];
            smf[rl * 132 + cl + 1] = acc[mt][nt][1];
            smf[(rl + 8) * 132 + cl]     = acc[mt][nt][2];
            smf[(rl + 8) * 132 + cl + 1] = acc[mt][nt][3];
        }
    __syncthreads();

    if (n0 < DMODEL) {                      // Q head: rope, hi/lo planes
        const int hh = n0 >> 7;
        #pragma unroll 4
        for (int it = 0; it < 32; it++) {
            int idx = it * 256 + tid;
            int r = idx >> 6, dd = idx & 63;
            int s = m0 + r;
            float x0 = smf[r * 132 + dd], x1 = smf[r * 132 + dd + 64];
            float c0 = cosp[s * HD + dd],      s0 = sinp[s * HD + dd];
            float c1 = cosp[s * HD + dd + 64], s1 = sinp[s * HD + dd + 64];
            float y0 = x0 * c0 - x1 * s0;
            float y1 = x1 * c1 + x0 * s1;
            size_t off = (size_t)s * DMODEL + hh * HD;
            __half h0 = __float2half(y0), h1 = __float2half(y1);
            g_Qhi[off + dd] = h0;
            g_Qlo[off + dd] = __float2half(y0 - __half2float(h0));
            g_Qhi[off + dd + 64] = h1;
            g_Qlo[off + dd + 64] = __float2half(y1 - __half2float(h1));
        }
    } else if (n0 < DMODEL + KV_DIM) {      // K head: rope, single plane
        const int kvh = (n0 - DMODEL) >> 7;
        #pragma unroll 4
        for (int it = 0; it < 32; it++) {
            int idx = it * 256 + tid;
            int r = idx >> 6, dd = idx & 63;
            int s = m0 + r;
            float x0 = smf[r * 132 + dd], x1 = smf[r * 132 + dd + 64];
            float c0 = cosp[s * HD + dd],      s0 = sinp[s * HD + dd];
            float c1 = cosp[s * HD + dd + 64], s1 = sinp[s * HD + dd + 64];
            size_t off = (size_t)s * KV_DIM + kvh * HD;
            g_Kh[off + dd]      = __float2half(x0 * c0 - x1 * s0);
            g_Kh[off + dd + 64] = __float2half(x1 * c1 + x0 * s1);
        }
    } else {                                // V head: plain convert
        const int vh2 = (n0 - DMODEL - KV_DIM) >> 7;
        #pragma unroll 4
        for (int it = 0; it < 32; it++) {
            int idx = it * 256 + tid;
            int r = idx >> 6, dd = idx & 63;
            int s = m0 + r;
            size_t off = (size_t)s * KV_DIM + vh2 * HD;
            g_Vh[off + dd]      = __float2half(smf[r * 132 + dd]);
            g_Vh[off + dd + 64] = __float2half(smf[r * 132 + dd + 64]);
        }
    }
}

// ---------------------------------------------------------------------------
// Tensor-core flash attention v5 (unchanged from R14 passing version)
// ---------------------------------------------------------------------------
#define FS_STRIDE   272
#define FKV_PLANE   (64 * FS_STRIDE)    // 17408
#define FS_STAGE    (2 * FKV_PLANE)     // 34816: Kh, Vh
#define FLASH_SMEM  (3 * FS_STAGE)      // 104448 -> 2 CTA/SM

__global__ __launch_bounds__(128, 2) void flash_mma()
{
    extern __shared__ char dsm[];
    const uint32_t sS = smem_u32(dsm);

    const int tid = threadIdx.x, lane = tid & 31, w = tid >> 5;
    const int qb = gridDim.x - 1 - blockIdx.x;
    const int h  = blockIdx.y;
    const int kvh = h >> 2;
    const int q0 = qb * 64;
    const float scale = 0.08838834764831845f;

    const uint32_t ldrow = lane & 15;
    const uint32_t ldoff = (lane >> 4) * 16;

    uint32_t qf[8][2][4];
    {
        const __half* qsrc[2] = { g_Qhi, g_Qlo };
        #pragma unroll
        for (int it = 0; it < 16; it++) {
            int idx = it * 128 + tid;
            int pl = idx >> 10, rem = idx & 1023;
            int r = rem >> 4, c = rem & 15;
            cp_async16(sS + pl * FKV_PLANE + r * FS_STRIDE + c * 16,
                       qsrc[pl] + (size_t)(q0 + r) * DMODEL + h * HD + c * 8);
        }
        CP_COMMIT();
        CP_WAIT(0);
        __syncthreads();
        #pragma unroll
        for (int kt = 0; kt < 8; kt++) {
            uint32_t qaddr = sS + (w * 16 + ldrow) * FS_STRIDE + kt * 32 + ldoff;
            ldm_x4(qf[kt][0][0], qf[kt][0][1], qf[kt][0][2], qf[kt][0][3], qaddr);
            ldm_x4(qf[kt][1][0], qf[kt][1][1], qf[kt][1][2], qf[kt][1][3],
                   qaddr + FKV_PLANE);
        }
        __syncthreads();
    }

    auto load_stage = [&](int stg, int k0) {
        const __half* src[2] = { g_Kh, g_Vh };
        uint32_t base = sS + stg * FS_STAGE;
        #pragma unroll
        for (int it = 0; it < 16; it++) {
            int idx = it * 128 + tid;
            int tile = idx >> 10, rem = idx & 1023;
            int r = rem >> 4, c = rem & 15;
            cp_async16(base + tile * FKV_PLANE + r * FS_STRIDE + c * 16,
                       src[tile] + (size_t)(k0 + r) * KV_DIM + kvh * HD + c * 8);
        }
        CP_COMMIT();
    };

    const int niter = qb + 1;
    load_stage(0, 0);
    if (niter > 1) load_stage(1, 64);

    float o[16][4];
    #pragma unroll
    for (int t = 0; t < 16; t++)
        #pragma unroll
        for (int e = 0; e < 4; e++) o[t][e] = 0.f;
    float m0 = -1e30f, m1 = -1e30f, l0 = 0.f, l1 = 0.f;

    const int rlow = q0 + w * 16 + (lane >> 2);

    for (int kb = 0; kb < niter; kb++) {
        if (kb + 1 < niter) { CP_WAIT(1); }
        else                { CP_WAIT(0); }
        __syncthreads();
        if (kb + 2 < niter) load_stage((kb + 2) % 3, (kb + 2) * 64);

        const uint32_t st = sS + (kb % 3) * FS_STAGE;

        float s_acc[8][4];
        #pragma unroll
        for (int t = 0; t < 8; t++)
            #pragma unroll
            for (int e = 0; e < 4; e++) s_acc[t][e] = 0.f;

        #pragma unroll
        for (int kt = 0; kt < 8; kt++) {
            uint32_t kh_[4][4];
            #pragma unroll
            for (int nt2 = 0; nt2 < 4; nt2++) {
                uint32_t kaddr = st + (nt2 * 16 + ldrow) * FS_STRIDE + kt * 32 + ldoff;
                ldm_x4(kh_[nt2][0], kh_[nt2][1], kh_[nt2][2], kh_[nt2][3], kaddr);
            }
            #pragma unroll
            for (int nt2 = 0; nt2 < 4; nt2++)
                #pragma unroll
                for (int sub = 0; sub < 2; sub++) {
                    float* d = s_acc[nt2 * 2 + sub];
                    mma_f16(d[0], d[1], d[2], d[3],
                            qf[kt][0][0], qf[kt][0][1], qf[kt][0][2], qf[kt][0][3],
                            kh_[nt2][sub], kh_[nt2][sub + 2]);
                }
            #pragma unroll
            for (int nt2 = 0; nt2 < 4; nt2++)
                #pragma unroll
                for (int sub = 0; sub < 2; sub++) {
                    float* d = s_acc[nt2 * 2 + sub];
                    mma_f16(d[0], d[1], d[2], d[3],
                            qf[kt][1][0], qf[kt][1][1], qf[kt][1][2], qf[kt][1][3],
                            kh_[nt2][sub], kh_[nt2][sub + 2]);
                }
        }

        const bool needmask = (kb == qb);
        const int colb = kb * 64 + (lane & 3) * 2;
        #pragma unroll
        for (int t = 0; t < 8; t++) {
            #pragma unroll
            for (int e = 0; e < 4; e++) {
                float v = s_acc[t][e] * scale;
                if (needmask) {
                    int col = colb + t * 8 + (e & 1);
                    int row = rlow + ((e >= 2) ? 8 : 0);
                    if (col > row) v = -1e30f;
                }
                s_acc[t][e] = v;
            }
        }

        float rmax0 = -1e30f, rmax1 = -1e30f;
        #pragma unroll
        for (int t = 0; t < 8; t++) {
            rmax0 = fmaxf(rmax0, fmaxf(s_acc[t][0], s_acc[t][1]));
            rmax1 = fmaxf(rmax1, fmaxf(s_acc[t][2], s_acc[t][3]));
        }
        #pragma unroll
        for (int off = 1; off <= 2; off <<= 1) {
            rmax0 = fmaxf(rmax0, __shfl_xor_sync(0xffffffffu, rmax0, off));
            rmax1 = fmaxf(rmax1, __shfl_xor_sync(0xffffffffu, rmax1, off));
        }
        float mn0 = fmaxf(m0, rmax0), mn1 = fmaxf(m1, rmax1);
        float al0 = __expf(m0 - mn0), al1 = __expf(m1 - mn1);
        float sum0 = 0.f, sum1 = 0.f;
        #pragma unroll
        for (int t = 0; t < 8; t++) {
            float p0 = __expf(s_acc[t][0] - mn0);
            float p1 = __expf(s_acc[t][1] - mn0);
            float p2 = __expf(s_acc[t][2] - mn1);
            float p3 = __expf(s_acc[t][3] - mn1);
            s_acc[t][0] = p0; s_acc[t][1] = p1; s_acc[t][2] = p2; s_acc[t][3] = p3;
            sum0 += p0 + p1; sum1 += p2 + p3;
        }
        #pragma unroll
        for (int off = 1; off <= 2; off <<= 1) {
            sum0 += __shfl_xor_sync(0xffffffffu, sum0, off);
            sum1 += __shfl_xor_sync(0xffffffffu, sum1, off);
        }
        l0 = l0 * al0 + sum0;  m0 = mn0;
        l1 = l1 * al1 + sum1;  m1 = mn1;
        #pragma unroll
        for (int t = 0; t < 16; t++) {
            o[t][0] *= al0; o[t][1] *= al0;
            o[t][2] *= al1; o[t][3] *= al1;
        }

        #pragma unroll
        for (int j = 0; j < 4; j++) {
            float lx[8];
            uint32_t ah[4], alr[4];
            ah[0] = pack_hi(s_acc[2*j][0],   s_acc[2*j][1],   lx[0], lx[1]);
            ah[1] = pack_hi(s_acc[2*j][2],   s_acc[2*j][3],   lx[2], lx[3]);
            ah[2] = pack_hi(s_acc[2*j+1][0], s_acc[2*j+1][1], lx[4], lx[5]);
            ah[3] = pack_hi(s_acc[2*j+1][2], s_acc[2*j+1][3], lx[6], lx[7]);
            alr[0] = pack_h(lx[0], lx[1]);
            alr[1] = pack_h(lx[2], lx[3]);
            alr[2] = pack_h(lx[4], lx[5]);
            alr[3] = pack_h(lx[6], lx[7]);

            #pragma unroll
            for (int g = 0; g < 2; g++) {
                uint32_t vh4[4][4];
                #pragma unroll
                for (int q4 = 0; q4 < 4; q4++) {
                    int dt2 = g * 4 + q4;
                    uint32_t vaddr = st + FKV_PLANE +
                                     (j * 16 + ldrow) * FS_STRIDE + dt2 * 32 + ldoff;
                    ldm_x4_t(vh4[q4][0], vh4[q4][1], vh4[q4][2], vh4[q4][3], vaddr);
                }
                #pragma unroll
                for (int q4 = 0; q4 < 4; q4++)
                    #pragma unroll
                    for (int sub = 0; sub < 2; sub++) {
                        float* d = o[(g * 4 + q4) * 2 + sub];
                        mma_f16(d[0], d[1], d[2], d[3],
                                ah[0], ah[1], ah[2], ah[3],
                                vh4[q4][2*sub], vh4[q4][2*sub+1]);
                    }
                #pragma unroll
                for (int q4 = 0; q4 < 4; q4++)
                    #pragma unroll
                    for (int sub = 0; sub < 2; sub++) {
                        float* d = o[(g * 4 + q4) * 2 + sub];
                        mma_f16(d[0], d[1], d[2], d[3],
                                alr[0], alr[1], alr[2], alr[3],
                                vh4[q4][2*sub], vh4[q4][2*sub+1]);
                    }
            }
        }
    }

    float inv0 = 1.0f / l0, inv1 = 1.0f / l1;
    const int row0 = q0 + w * 16 + (lane >> 2);
    #pragma unroll
    for (int t = 0; t < 16; t++) {
        int d = t * 8 + (lane & 3) * 2;
        size_t off0 = (size_t)row0 * DMODEL + h * HD + d;
        size_t off1 = off0 + 8 * DMODEL;
        float v0 = o[t][0] * inv0, v1 = o[t][1] * inv0;
        float v2 = o[t][2] * inv1, v3 = o[t][3] * inv1;
        __half h0 = __float2half(v0), h1 = __float2half(v1);
        __half h2 = __float2half(v2), h3 = __float2half(v3);
        *(__half2*)&g_Ohi[off0] = __halves2half2(h0, h1);
        *(__half2*)&g_Ohi[off1] = __halves2half2(h2, h3);
        *(__half2*)&g_Olo[off0] = __halves2half2(
            __float2half(v0 - __half2float(h0)),
            __float2half(v1 - __half2float(h1)));
        *(__half2*)&g_Olo[off1] = __halves2half2(
            __float2half(v2 - __half2float(h2)),
            __float2half(v3 - __half2float(h3)));
    }
}

// ---------------------------------------------------------------------------
extern "C" void kernel_launch(void* const* d_in, const int* in_sizes, int n_in,
                              void* d_out, int out_size)
{
    const float* X    = (const float*)d_in[0];
    const float* cosp = (const float*)d_in[1];
    const float* sinp = (const float*)d_in[2];
    const float* Wq   = (const float*)d_in[3];
    const float* Wk   = (const float*)d_in[4];
    const float* Wv   = (const float*)d_in[5];
    const float* Wo   = (const float*)d_in[6];
    float* out = (float*)d_out;

    __half *xh, *xl, *oh, *ol, *qkvw, *wow;
    cudaGetSymbolAddress((void**)&xh, g_Xhi);   cudaGetSymbolAddress((void**)&xl, g_Xlo);
    cudaGetSymbolAddress((void**)&oh, g_Ohi);   cudaGetSymbolAddress((void**)&ol, g_Olo);
    cudaGetSymbolAddress((void**)&qkvw, g_WqkvT);
    cudaGetSymbolAddress((void**)&wow, g_WoT);

    cudaFuncSetAttribute(gemm_mma, cudaFuncAttributeMaxDynamicSharedMemorySize, GEMM_SMEM);
    cudaFuncSetAttribute(flash_mma, cudaFuncAttributeMaxDynamicSharedMemorySize, FLASH_SMEM);

    // #1 split X -> fp16 hi/lo
    split_rm<<<(S_LEN * DMODEL + 255) / 256, 256>>>(X, xh, xl, S_LEN * DMODEL);
    // #2 fused transpose Wq/Wk/Wv
    split_tr3<<<dim3(96, 64), 256>>>(Wq, Wk, Wv, qkvw);
    // #3 transpose Wo
    split_tr<<<dim3(DMODEL / 32, DMODEL / 32), 256>>>(Wo, wow, DMODEL, DMODEL);
    // #4 fused QKV projection + RoPE + split epilogue (mode 1)
    gemm_mma<<<dim3(NQKV / 128, S_LEN / 128), 256, GEMM_SMEM>>>(
        xh, xl, qkvw, nullptr, cosp, sinp, S_LEN, NQKV, DMODEL, 1);
    // #5 flash attention v5 (BN=64)
    flash_mma<<<dim3(S_LEN / 64, NH), 128, FLASH_SMEM>>>();
    // #6 output projection (mode 0)
    gemm_mma<<<dim3(DMODEL / 128, S_LEN / 128), 256, GEMM_SMEM>>>(
        oh, ol, wow, out, nullptr, nullptr, S_LEN, DMODEL, DMODEL, 0);
}

// round 16
// speedup vs baseline: 1.4892x; 1.4892x over previous
#include <cuda_runtime.h>
#include <cuda_fp16.h>
#include <cstdint>
#include <math.h>

#define S_LEN   4096
#define DMODEL  2048
#define NH      16
#define NKV     4
#define HD      128
#define KV_DIM  (NKV * HD)        // 512
#define NQKV    (DMODEL + 2 * KV_DIM)   // 3072

// ---------------- device scratch (allocation-free rule) ----------------
__device__ float g_QKV[S_LEN * NQKV];

__device__ __half g_Xhi[S_LEN * DMODEL];
__device__ __half g_Xlo[S_LEN * DMODEL];
__device__ __half g_Qhi[S_LEN * DMODEL];
__device__ __half g_Qlo[S_LEN * DMODEL];
__device__ __half g_Kh[S_LEN * KV_DIM];
__device__ __half g_Vh[S_LEN * KV_DIM];
__device__ __half g_Ohi[S_LEN * DMODEL];
__device__ __half g_Olo[S_LEN * DMODEL];
__device__ __half g_WqkvT[NQKV * DMODEL];
__device__ __half g_WoT[DMODEL * DMODEL];

// ---------------- PTX helpers (compute_103-safe: sm_80-era ISA) ----------------
__device__ __forceinline__ uint32_t smem_u32(const void* p) {
    uint32_t a;
    asm("{ .reg .u64 t; cvta.to.shared.u64 t, %1; cvt.u32.u64 %0, t; }"
        : "=r"(a) : "l"(p));
    return a;
}
__device__ __forceinline__ void cp_async16(uint32_t dst, const void* src) {
    asm volatile("cp.async.cg.shared.global [%0], [%1], 16;" :: "r"(dst), "l"(src));
}
#define CP_COMMIT() asm volatile("cp.async.commit_group;" ::: "memory")
#define CP_WAIT(n)  asm volatile("cp.async.wait_group %0;" :: "n"(n) : "memory")

__device__ __forceinline__ void ldm_x4(uint32_t& r0, uint32_t& r1, uint32_t& r2,
                                       uint32_t& r3, uint32_t addr) {
    asm volatile("ldmatrix.sync.aligned.m8n8.x4.shared.b16 {%0,%1,%2,%3}, [%4];"
                 : "=r"(r0), "=r"(r1), "=r"(r2), "=r"(r3) : "r"(addr));
}
__device__ __forceinline__ void ldm_x4_t(uint32_t& r0, uint32_t& r1, uint32_t& r2,
                                         uint32_t& r3, uint32_t addr) {
    asm volatile("ldmatrix.sync.aligned.m8n8.x4.trans.shared.b16 {%0,%1,%2,%3}, [%4];"
                 : "=r"(r0), "=r"(r1), "=r"(r2), "=r"(r3) : "r"(addr));
}
__device__ __forceinline__ void mma_f16(float& d0, float& d1, float& d2, float& d3,
                                        uint32_t a0, uint32_t a1, uint32_t a2,
                                        uint32_t a3, uint32_t b0, uint32_t b1) {
    asm volatile(
        "mma.sync.aligned.m16n8k16.row.col.f32.f16.f16.f32 "
        "{%0,%1,%2,%3}, {%4,%5,%6,%7}, {%8,%9}, {%0,%1,%2,%3};"
        : "+f"(d0), "+f"(d1), "+f"(d2), "+f"(d3)
        : "r"(a0), "r"(a1), "r"(a2), "r"(a3), "r"(b0), "r"(b1));
}
__device__ __forceinline__ uint32_t pack_hi(float x, float y, float& rx, float& ry) {
    __half hx = __float2half(x), hy = __float2half(y);
    rx = x - __half2float(hx);
    ry = y - __half2float(hy);
    __half2 p = __halves2half2(hx, hy);
    return *(uint32_t*)&p;
}
__device__ __forceinline__ uint32_t pack_h(float x, float y) {
    __half2 p = __halves2half2(__float2half(x), __float2half(y));
    return *(uint32_t*)&p;
}
__device__ __forceinline__ uint32_t swz64(uint32_t o) {
    return o ^ ((o >> 3) & 0x30);
}

// ---------------------------------------------------------------------------
// Vectorized split fp32 -> (fp16 hi, fp16 lo): 4 elements per thread
// ---------------------------------------------------------------------------
__global__ void split_rm4(const float4* __restrict__ src,
                          __half2* __restrict__ hi,
                          __half2* __restrict__ lo, int n4)
{
    int i = blockIdx.x * blockDim.x + threadIdx.x;
    if (i >= n4) return;
    float4 f = src[i];
    __half hx = __float2half(f.x), hy = __float2half(f.y);
    __half hz = __float2half(f.z), hw = __float2half(f.w);
    hi[2 * i]     = __halves2half2(hx, hy);
    hi[2 * i + 1] = __halves2half2(hz, hw);
    lo[2 * i]     = __halves2half2(__float2half(f.x - __half2float(hx)),
                                   __float2half(f.y - __half2float(hy)));
    lo[2 * i + 1] = __halves2half2(__float2half(f.z - __half2float(hz)),
                                   __float2half(f.w - __half2float(hw)));
}

// ---------------------------------------------------------------------------
// Merged transpose of Wq,Wk,Wv,Wo -> g_WqkvT / g_WoT fp16 [N,K] (K=DMODEL)
// grid (160, 64): bx<64 Wq, <80 Wk, <96 Wv, else Wo.
// ---------------------------------------------------------------------------
__global__ __launch_bounds__(256) void split_trA(const float* __restrict__ Wq,
                                                 const float* __restrict__ Wk,
                                                 const float* __restrict__ Wv,
                                                 const float* __restrict__ Wo,
                                                 __half* __restrict__ qkvT,
                                                 __half* __restrict__ woT)
{
    const int bx = blockIdx.x;
    const float* W; int N, n0; __half* dst; int dro;
    if (bx < 64)      { W = Wq; N = DMODEL; n0 = bx * 32;        dst = qkvT; dro = 0; }
    else if (bx < 80) { W = Wk; N = KV_DIM; n0 = (bx - 64) * 32; dst = qkvT; dro = DMODEL; }
    else if (bx < 96) { W = Wv; N = KV_DIM; n0 = (bx - 80) * 32; dst = qkvT; dro = DMODEL + KV_DIM; }
    else              { W = Wo; N = DMODEL; n0 = (bx - 96) * 32; dst = woT;  dro = 0; }

    __shared__ float s[32][33];
    int k0 = blockIdx.y * 32;
    int tx = threadIdx.x & 31, ty = threadIdx.x >> 5;
    #pragma unroll
    for (int j = 0; j < 4; j++)
        s[ty + j * 8][tx] = W[(size_t)(k0 + ty + j * 8) * N + n0 + tx];
    __syncthreads();
    #pragma unroll
    for (int j = 0; j < 4; j++) {
        int nn = ty + j * 8;
        dst[(size_t)(dro + n0 + nn) * DMODEL + k0 + tx] = __float2half(s[tx][nn]);
    }
}

// ---------------------------------------------------------------------------
// mma.sync fp16x2 GEMM (R13/R14-proven): C = (Ahi+Alo) @ (B[N,K])^T, fp32 out.
// CTA 128x128, BK=32, 8 warps, 3-stage cp.async pipeline, 2 CTA/SM.
// ---------------------------------------------------------------------------
#define GS_TILE   8192
#define GS_STAGE  24576
#define GEMM_SMEM 73728

__global__ __launch_bounds__(256, 2) void gemm_mma(
    const __half* __restrict__ Ahi, const __half* __restrict__ Alo,
    const __half* __restrict__ B,
    float* __restrict__ C, int M, int N, int K)
{
    extern __shared__ char dsm[];
    const uint32_t sbase = smem_u32(dsm);

    const int tid  = threadIdx.x;
    const int lane = tid & 31;
    const int w    = tid >> 5;
    const int wm   = w >> 2;
    const int wn   = w & 3;
    const int n0 = blockIdx.x * 128, m0 = blockIdx.y * 128;

    const __half* srcs[3] = {
        Ahi + (size_t)m0 * K, Alo + (size_t)m0 * K, B + (size_t)n0 * K };

    auto load_stage = [&](int stg, int kk) {
        uint32_t sb = sbase + stg * GS_STAGE;
        #pragma unroll
        for (int it = 0; it < 6; it++) {
            int idx  = it * 256 + tid;
            int tile = idx / 512;
            int rem  = idx & 511;
            int r    = rem >> 2;
            int c    = rem & 3;
            cp_async16(sb + tile * GS_TILE + swz64(r * 64 + c * 16),
                       srcs[tile] + (size_t)r * K + kk + c * 8);
        }
        CP_COMMIT();
    };

    float acc[4][4][4];
    #pragma unroll
    for (int i = 0; i < 4; i++)
        #pragma unroll
        for (int j = 0; j < 4; j++)
            #pragma unroll
            for (int q = 0; q < 4; q++) acc[i][j][q] = 0.f;

    const int ns = K >> 5;
    load_stage(0, 0);
    load_stage(1, 32);

    const uint32_t ldr = (lane & 15);
    const uint32_t ldc = (lane >> 4) * 16;

    for (int i = 0; i < ns; i++) {
        if (i + 1 < ns) { CP_WAIT(1); }
        else            { CP_WAIT(0); }
        __syncthreads();
        if (i + 2 < ns) load_stage((i + 2) % 3, (i + 2) * 32);

        const uint32_t sA = sbase + (i % 3) * GS_STAGE;
        const uint32_t sB = sA + 2 * GS_TILE;

        #pragma unroll
        for (int ks = 0; ks < 2; ks++) {
            const uint32_t kboff = ks * 32 + ldc;
            uint32_t af[2][4][4];
            #pragma unroll
            for (int p = 0; p < 2; p++)
                #pragma unroll
                for (int mt = 0; mt < 4; mt++)
                    ldm_x4(af[p][mt][0], af[p][mt][1], af[p][mt][2], af[p][mt][3],
                           sA + p * GS_TILE +
                           swz64((wm * 64 + mt * 16 + ldr) * 64 + kboff));

            #pragma unroll
            for (int nh = 0; nh < 2; nh++) {
                uint32_t bfr[4];
                ldm_x4(bfr[0], bfr[1], bfr[2], bfr[3],
                       sB + swz64((wn * 32 + nh * 16 + ldr) * 64 + kboff));

                #pragma unroll
                for (int mt = 0; mt < 4; mt++)
                    #pragma unroll
                    for (int sub = 0; sub < 2; sub++) {
                        float* d = acc[mt][nh * 2 + sub];
                        mma_f16(d[0], d[1], d[2], d[3],
                                af[0][mt][0], af[0][mt][1], af[0][mt][2], af[0][mt][3],
                                bfr[sub], bfr[sub + 2]);
                    }
                #pragma unroll
                for (int mt = 0; mt < 4; mt++)
                    #pragma unroll
                    for (int sub = 0; sub < 2; sub++) {
                        float* d = acc[mt][nh * 2 + sub];
                        mma_f16(d[0], d[1], d[2], d[3],
                                af[1][mt][0], af[1][mt][1], af[1][mt][2], af[1][mt][3],
                                bfr[sub], bfr[sub + 2]);
                    }
            }
        }
    }

    const int trow = lane >> 2;
    const int tcol = (lane & 3) * 2;
    #pragma unroll
    for (int mt = 0; mt < 4; mt++) {
        #pragma unroll
        for (int nt = 0; nt < 4; nt++) {
            const int rr = m0 + wm * 64 + mt * 16 + trow;
            const int cc = n0 + wn * 32 + nt * 8 + tcol;
            *(float2*)&C[(size_t)rr * N + cc] =
                make_float2(acc[mt][nt][0], acc[mt][nt][1]);
            *(float2*)&C[(size_t)(rr + 8) * N + cc] =
                make_float2(acc[mt][nt][2], acc[mt][nt][3]);
        }
    }
}

// ---------------------------------------------------------------------------
// RoPE + split from fused g_QKV (R14-proven)
// ---------------------------------------------------------------------------
__global__ void rope_split2(const float* __restrict__ cosp,
                            const float* __restrict__ sinp)
{
    const int per_s = (NH + 2 * NKV) * 64;
    int idx = blockIdx.x * blockDim.x + threadIdx.x;
    if (idx >= S_LEN * per_s) return;
    int s = idx / per_s;
    int r = idx % per_s;
    int hh = r >> 6;
    int d = r & 63;

    const float* row = g_QKV + (size_t)s * NQKV;

    if (hh < NH) {
        const float* p = row + hh * HD;
        size_t off = (size_t)s * DMODEL + hh * HD;
        float c0 = cosp[s * HD + d],      s0 = sinp[s * HD + d];
        float c1 = cosp[s * HD + d + 64], s1 = sinp[s * HD + d + 64];
        float x0 = p[d], x1 = p[d + 64];
        float y0 = x0 * c0 - x1 * s0;
        float y1 = x1 * c1 + x0 * s1;
        __half h0 = __float2half(y0), h1 = __float2half(y1);
        g_Qhi[off + d] = h0;      g_Qlo[off + d] = __float2half(y0 - __half2float(h0));
        g_Qhi[off + d + 64] = h1; g_Qlo[off + d + 64] = __float2half(y1 - __half2float(h1));
    } else if (hh < NH + NKV) {
        int kh2 = hh - NH;
        const float* p = row + DMODEL + kh2 * HD;
        size_t off = (size_t)s * KV_DIM + kh2 * HD;
        float c0 = cosp[s * HD + d],      s0 = sinp[s * HD + d];
        float c1 = cosp[s * HD + d + 64], s1 = sinp[s * HD + d + 64];
        float x0 = p[d], x1 = p[d + 64];
        g_Kh[off + d]      = __float2half(x0 * c0 - x1 * s0);
        g_Kh[off + d + 64] = __float2half(x1 * c1 + x0 * s1);
    } else {
        int vh2 = hh - NH - NKV;
        const float* p = row + DMODEL + KV_DIM + vh2 * HD;
        size_t off = (size_t)s * KV_DIM + vh2 * HD;
        g_Vh[off + d]      = __float2half(p[d]);
        g_Vh[off + d + 64] = __float2half(p[d + 64]);
    }
}

// ---------------------------------------------------------------------------
// Tensor-core flash attention v5 (R14-proven): fp16x2, fp32 softmax/accum,
// CTA 64 q-rows x 1 head, 128 threads, BN=64, 3-stage KV pipeline, 2 CTA/SM.
// ---------------------------------------------------------------------------
#define FS_STRIDE   272
#define FKV_PLANE   (64 * FS_STRIDE)    // 17408
#define FS_STAGE    (2 * FKV_PLANE)     // 34816: Kh, Vh
#define FLASH_SMEM  (3 * FS_STAGE)      // 104448 -> 2 CTA/SM

__global__ __launch_bounds__(128, 2) void flash_mma()
{
    extern __shared__ char dsm[];
    const uint32_t sS = smem_u32(dsm);

    const int tid = threadIdx.x, lane = tid & 31, w = tid >> 5;
    const int qb = gridDim.x - 1 - blockIdx.x;
    const int h  = blockIdx.y;
    const int kvh = h >> 2;
    const int q0 = qb * 64;
    const float scale = 0.08838834764831845f;

    const uint32_t ldrow = lane & 15;
    const uint32_t ldoff = (lane >> 4) * 16;

    uint32_t qf[8][2][4];
    {
        const __half* qsrc[2] = { g_Qhi, g_Qlo };
        #pragma unroll
        for (int it = 0; it < 16; it++) {
            int idx = it * 128 + tid;
            int pl = idx >> 10, rem = idx & 1023;
            int r = rem >> 4, c = rem & 15;
            cp_async16(sS + pl * FKV_PLANE + r * FS_STRIDE + c * 16,
                       qsrc[pl] + (size_t)(q0 + r) * DMODEL + h * HD + c * 8);
        }
        CP_COMMIT();
        CP_WAIT(0);
        __syncthreads();
        #pragma unroll
        for (int kt = 0; kt < 8; kt++) {
            uint32_t qaddr = sS + (w * 16 + ldrow) * FS_STRIDE + kt * 32 + ldoff;
            ldm_x4(qf[kt][0][0], qf[kt][0][1], qf[kt][0][2], qf[kt][0][3], qaddr);
            ldm_x4(qf[kt][1][0], qf[kt][1][1], qf[kt][1][2], qf[kt][1][3],
                   qaddr + FKV_PLANE);
        }
        __syncthreads();
    }

    auto load_stage = [&](int stg, int k0) {
        const __half* src[2] = { g_Kh, g_Vh };
        uint32_t base = sS + stg * FS_STAGE;
        #pragma unroll
        for (int it = 0; it < 16; it++) {
            int idx = it * 128 + tid;
            int tile = idx >> 10, rem = idx & 1023;
            int r = rem >> 4, c = rem & 15;
            cp_async16(base + tile * FKV_PLANE + r * FS_STRIDE + c * 16,
                       src[tile] + (size_t)(k0 + r) * KV_DIM + kvh * HD + c * 8);
        }
        CP_COMMIT();
    };

    const int niter = qb + 1;
    load_stage(0, 0);
    if (niter > 1) load_stage(1, 64);

    float o[16][4];
    #pragma unroll
    for (int t = 0; t < 16; t++)
        #pragma unroll
        for (int e = 0; e < 4; e++) o[t][e] = 0.f;
    float m0 = -1e30f, m1 = -1e30f, l0 = 0.f, l1 = 0.f;

    const int rlow = q0 + w * 16 + (lane >> 2);

    for (int kb = 0; kb < niter; kb++) {
        if (kb + 1 < niter) { CP_WAIT(1); }
        else                { CP_WAIT(0); }
        __syncthreads();
        if (kb + 2 < niter) load_stage((kb + 2) % 3, (kb + 2) * 64);

        const uint32_t st = sS + (kb % 3) * FS_STAGE;

        float s_acc[8][4];
        #pragma unroll
        for (int t = 0; t < 8; t++)
            #pragma unroll
            for (int e = 0; e < 4; e++) s_acc[t][e] = 0.f;

        #pragma unroll
        for (int kt = 0; kt < 8; kt++) {
            uint32_t kh_[4][4];
            #pragma unroll
            for (int nt2 = 0; nt2 < 4; nt2++) {
                uint32_t kaddr = st + (nt2 * 16 + ldrow) * FS_STRIDE + kt * 32 + ldoff;
                ldm_x4(kh_[nt2][0], kh_[nt2][1], kh_[nt2][2], kh_[nt2][3], kaddr);
            }
            #pragma unroll
            for (int nt2 = 0; nt2 < 4; nt2++)
                #pragma unroll
                for (int sub = 0; sub < 2; sub++) {
                    float* d = s_acc[nt2 * 2 + sub];
                    mma_f16(d[0], d[1], d[2], d[3],
                            qf[kt][0][0], qf[kt][0][1], qf[kt][0][2], qf[kt][0][3],
                            kh_[nt2][sub], kh_[nt2][sub + 2]);
                }
            #pragma unroll
            for (int nt2 = 0; nt2 < 4; nt2++)
                #pragma unroll
                for (int sub = 0; sub < 2; sub++) {
                    float* d = s_acc[nt2 * 2 + sub];
                    mma_f16(d[0], d[1], d[2], d[3],
                            qf[kt][1][0], qf[kt][1][1], qf[kt][1][2], qf[kt][1][3],
                            kh_[nt2][sub], kh_[nt2][sub + 2]);
                }
        }

        const bool needmask = (kb == qb);
        const int colb = kb * 64 + (lane & 3) * 2;
        #pragma unroll
        for (int t = 0; t < 8; t++) {
            #pragma unroll
            for (int e = 0; e < 4; e++) {
                float v = s_acc[t][e] * scale;
                if (needmask) {
                    int col = colb + t * 8 + (e & 1);
                    int row = rlow + ((e >= 2) ? 8 : 0);
                    if (col > row) v = -1e30f;
                }
                s_acc[t][e] = v;
            }
        }

        float rmax0 = -1e30f, rmax1 = -1e30f;
        #pragma unroll
        for (int t = 0; t < 8; t++) {
            rmax0 = fmaxf(rmax0, fmaxf(s_acc[t][0], s_acc[t][1]));
            rmax1 = fmaxf(rmax1, fmaxf(s_acc[t][2], s_acc[t][3]));
        }
        #pragma unroll
        for (int off = 1; off <= 2; off <<= 1) {
            rmax0 = fmaxf(rmax0, __shfl_xor_sync(0xffffffffu, rmax0, off));
            rmax1 = fmaxf(rmax1, __shfl_xor_sync(0xffffffffu, rmax1, off));
        }
        float mn0 = fmaxf(m0, rmax0), mn1 = fmaxf(m1, rmax1);
        float al0 = __expf(m0 - mn0), al1 = __expf(m1 - mn1);
        float sum0 = 0.f, sum1 = 0.f;
        #pragma unroll
        for (int t = 0; t < 8; t++) {
            float p0 = __expf(s_acc[t][0] - mn0);
            float p1 = __expf(s_acc[t][1] - mn0);
            float p2 = __expf(s_acc[t][2] - mn1);
            float p3 = __expf(s_acc[t][3] - mn1);
            s_acc[t][0] = p0; s_acc[t][1] = p1; s_acc[t][2] = p2; s_acc[t][3] = p3;
            sum0 += p0 + p1; sum1 += p2 + p3;
        }
        #pragma unroll
        for (int off = 1; off <= 2; off <<= 1) {
            sum0 += __shfl_xor_sync(0xffffffffu, sum0, off);
            sum1 += __shfl_xor_sync(0xffffffffu, sum1, off);
        }
        l0 = l0 * al0 + sum0;  m0 = mn0;
        l1 = l1 * al1 + sum1;  m1 = mn1;
        #pragma unroll
        for (int t = 0; t < 16; t++) {
            o[t][0] *= al0; o[t][1] *= al0;
            o[t][2] *= al1; o[t][3] *= al1;
        }

        #pragma unroll
        for (int j = 0; j < 4; j++) {
            float lx[8];
            uint32_t ah[4], alr[4];
            ah[0] = pack_hi(s_acc[2*j][0],   s_acc[2*j][1],   lx[0], lx[1]);
            ah[1] = pack_hi(s_acc[2*j][2],   s_acc[2*j][3],   lx[2], lx[3]);
            ah[2] = pack_hi(s_acc[2*j+1][0], s_acc[2*j+1][1], lx[4], lx[5]);
            ah[3] = pack_hi(s_acc[2*j+1][2], s_acc[2*j+1][3], lx[6], lx[7]);
            alr[0] = pack_h(lx[0], lx[1]);
            alr[1] = pack_h(lx[2], lx[3]);
            alr[2] = pack_h(lx[4], lx[5]);
            alr[3] = pack_h(lx[6], lx[7]);

            #pragma unroll
            for (int g = 0; g < 2; g++) {
                uint32_t vh4[4][4];
                #pragma unroll
                for (int q4 = 0; q4 < 4; q4++) {
                    int dt2 = g * 4 + q4;
                    uint32_t vaddr = st + FKV_PLANE +
                                     (j * 16 + ldrow) * FS_STRIDE + dt2 * 32 + ldoff;
                    ldm_x4_t(vh4[q4][0], vh4[q4][1], vh4[q4][2], vh4[q4][3], vaddr);
                }
                #pragma unroll
                for (int q4 = 0; q4 < 4; q4++)
                    #pragma unroll
                    for (int sub = 0; sub < 2; sub++) {
                        float* d = o[(g * 4 + q4) * 2 + sub];
                        mma_f16(d[0], d[1], d[2], d[3],
                                ah[0], ah[1], ah[2], ah[3],
                                vh4[q4][2*sub], vh4[q4][2*sub+1]);
                    }
                #pragma unroll
                for (int q4 = 0; q4 < 4; q4++)
                    #pragma unroll
                    for (int sub = 0; sub < 2; sub++) {
                        float* d = o[(g * 4 + q4) * 2 + sub];
                        mma_f16(d[0], d[1], d[2], d[3],
                                alr[0], alr[1], alr[2], alr[3],
                                vh4[q4][2*sub], vh4[q4][2*sub+1]);
                    }
            }
        }
    }

    float inv0 = 1.0f / l0, inv1 = 1.0f / l1;
    const int row0 = q0 + w * 16 + (lane >> 2);
    #pragma unroll
    for (int t = 0; t < 16; t++) {
        int d = t * 8 + (lane & 3) * 2;
        size_t off0 = (size_t)row0 * DMODEL + h * HD + d;
        size_t off1 = off0 + 8 * DMODEL;
        float v0 = o[t][0] * inv0, v1 = o[t][1] * inv0;
        float v2 = o[t][2] * inv1, v3 = o[t][3] * inv1;
        __half h0 = __float2half(v0), h1 = __float2half(v1);
        __half h2 = __float2half(v2), h3 = __float2half(v3);
        *(__half2*)&g_Ohi[off0] = __halves2half2(h0, h1);
        *(__half2*)&g_Ohi[off1] = __halves2half2(h2, h3);
        *(__half2*)&g_Olo[off0] = __halves2half2(
            __float2half(v0 - __half2float(h0)),
            __float2half(v1 - __half2float(h1)));
        *(__half2*)&g_Olo[off1] = __halves2half2(
            __float2half(v2 - __half2float(h2)),
            __float2half(v3 - __half2float(h3)));
    }
}

// ---------------------------------------------------------------------------
extern "C" void kernel_launch(void* const* d_in, const int* in_sizes, int n_in,
                              void* d_out, int out_size)
{
    const float* X    = (const float*)d_in[0];
    const float* cosp = (const float*)d_in[1];
    const float* sinp = (const float*)d_in[2];
    const float* Wq   = (const float*)d_in[3];
    const float* Wk   = (const float*)d_in[4];
    const float* Wv   = (const float*)d_in[5];
    const float* Wo   = (const float*)d_in[6];
    float* out = (float*)d_out;

    float* gqkv;
    cudaGetSymbolAddress((void**)&gqkv, g_QKV);
    __half *xh, *xl, *oh, *ol, *qkvw, *wow;
    cudaGetSymbolAddress((void**)&xh, g_Xhi);   cudaGetSymbolAddress((void**)&xl, g_Xlo);
    cudaGetSymbolAddress((void**)&oh, g_Ohi);   cudaGetSymbolAddress((void**)&ol, g_Olo);
    cudaGetSymbolAddress((void**)&qkvw, g_WqkvT);
    cudaGetSymbolAddress((void**)&wow, g_WoT);

    cudaFuncSetAttribute(gemm_mma, cudaFuncAttributeMaxDynamicSharedMemorySize, GEMM_SMEM);
    cudaFuncSetAttribute(flash_mma, cudaFuncAttributeMaxDynamicSharedMemorySize, FLASH_SMEM);

    // #1 split X -> fp16 hi/lo (vectorized)
    int n4 = S_LEN * DMODEL / 4;
    split_rm4<<<(n4 + 255) / 256, 256>>>((const float4*)X, (__half2*)xh,
                                         (__half2*)xl, n4);
    // #2 merged transpose Wq/Wk/Wv/Wo
    split_trA<<<dim3(160, 64), 256>>>(Wq, Wk, Wv, Wo, qkvw, wow);
    // #3 fused QKV projection
    gemm_mma<<<dim3(NQKV / 128, S_LEN / 128), 256, GEMM_SMEM>>>(
        xh, xl, qkvw, gqkv, S_LEN, NQKV, DMODEL);
    // #4 RoPE(Q,K) + V -> fp16 planes
    int rthreads = S_LEN * (NH + 2 * NKV) * 64;
    rope_split2<<<(rthreads + 255) / 256, 256>>>(cosp, sinp);
    // #5 flash attention v5 (BN=64)
    flash_mma<<<dim3(S_LEN / 64, NH), 128, FLASH_SMEM>>>();
    // #6 output projection
    gemm_mma<<<dim3(DMODEL / 128, S_LEN / 128), 256, GEMM_SMEM>>>(
        oh, ol, wow, out, S_LEN, DMODEL, DMODEL);
}

// round 17
// speedup vs baseline: 1.6600x; 1.1147x over previous
#include <cuda_runtime.h>
#include <cuda_fp16.h>
#include <cstdint>
#include <math.h>

#define S_LEN   4096
#define DMODEL  2048
#define NH      16
#define NKV     4
#define HD      128
#define KV_DIM  (NKV * HD)        // 512
#define NQKV    (DMODEL + 2 * KV_DIM)   // 3072

// ---------------- device scratch (allocation-free rule) ----------------
__device__ float g_QKV[S_LEN * NQKV];

__device__ __half g_Xhi[S_LEN * DMODEL];
__device__ __half g_Xlo[S_LEN * DMODEL];
__device__ __half g_Qhi[S_LEN * DMODEL];
__device__ __half g_Qlo[S_LEN * DMODEL];
__device__ __half g_Kh[S_LEN * KV_DIM];
__device__ __half g_Vh[S_LEN * KV_DIM];
__device__ __half g_Ohi[S_LEN * DMODEL];
__device__ __half g_Olo[S_LEN * DMODEL];
__device__ __half g_WqkvT[NQKV * DMODEL];
__device__ __half g_WoT[DMODEL * DMODEL];

// ---------------- PTX helpers (compute_103-safe: sm_80-era ISA) ----------------
__device__ __forceinline__ uint32_t smem_u32(const void* p) {
    uint32_t a;
    asm("{ .reg .u64 t; cvta.to.shared.u64 t, %1; cvt.u32.u64 %0, t; }"
        : "=r"(a) : "l"(p));
    return a;
}
__device__ __forceinline__ void cp_async16(uint32_t dst, const void* src) {
    asm volatile("cp.async.cg.shared.global [%0], [%1], 16;" :: "r"(dst), "l"(src));
}
#define CP_COMMIT() asm volatile("cp.async.commit_group;" ::: "memory")
#define CP_WAIT(n)  asm volatile("cp.async.wait_group %0;" :: "n"(n) : "memory")

__device__ __forceinline__ void ldm_x4(uint32_t& r0, uint32_t& r1, uint32_t& r2,
                                       uint32_t& r3, uint32_t addr) {
    asm volatile("ldmatrix.sync.aligned.m8n8.x4.shared.b16 {%0,%1,%2,%3}, [%4];"
                 : "=r"(r0), "=r"(r1), "=r"(r2), "=r"(r3) : "r"(addr));
}
__device__ __forceinline__ void ldm_x4_t(uint32_t& r0, uint32_t& r1, uint32_t& r2,
                                         uint32_t& r3, uint32_t addr) {
    asm volatile("ldmatrix.sync.aligned.m8n8.x4.trans.shared.b16 {%0,%1,%2,%3}, [%4];"
                 : "=r"(r0), "=r"(r1), "=r"(r2), "=r"(r3) : "r"(addr));
}
__device__ __forceinline__ void mma_f16(float& d0, float& d1, float& d2, float& d3,
                                        uint32_t a0, uint32_t a1, uint32_t a2,
                                        uint32_t a3, uint32_t b0, uint32_t b1) {
    asm volatile(
        "mma.sync.aligned.m16n8k16.row.col.f32.f16.f16.f32 "
        "{%0,%1,%2,%3}, {%4,%5,%6,%7}, {%8,%9}, {%0,%1,%2,%3};"
        : "+f"(d0), "+f"(d1), "+f"(d2), "+f"(d3)
        : "r"(a0), "r"(a1), "r"(a2), "r"(a3), "r"(b0), "r"(b1));
}
__device__ __forceinline__ uint32_t pack_hi(float x, float y, float& rx, float& ry) {
    __half hx = __float2half(x), hy = __float2half(y);
    rx = x - __half2float(hx);
    ry = y - __half2float(hy);
    __half2 p = __halves2half2(hx, hy);
    return *(uint32_t*)&p;
}
__device__ __forceinline__ uint32_t pack_h(float x, float y) {
    __half2 p = __halves2half2(__float2half(x), __float2half(y));
    return *(uint32_t*)&p;
}
__device__ __forceinline__ uint32_t swz64(uint32_t o) {
    return o ^ ((o >> 3) & 0x30);
}

// ---------------------------------------------------------------------------
// Vectorized split fp32 -> (fp16 hi, fp16 lo): 4 elements per thread
// ---------------------------------------------------------------------------
__global__ void split_rm4(const float4* __restrict__ src,
                          __half2* __restrict__ hi,
                          __half2* __restrict__ lo, int n4)
{
    int i = blockIdx.x * blockDim.x + threadIdx.x;
    if (i >= n4) return;
    float4 f = src[i];
    __half hx = __float2half(f.x), hy = __float2half(f.y);
    __half hz = __float2half(f.z), hw = __float2half(f.w);
    hi[2 * i]     = __halves2half2(hx, hy);
    hi[2 * i + 1] = __halves2half2(hz, hw);
    lo[2 * i]     = __halves2half2(__float2half(f.x - __half2float(hx)),
                                   __float2half(f.y - __half2float(hy)));
    lo[2 * i + 1] = __halves2half2(__float2half(f.z - __half2float(hz)),
                                   __float2half(f.w - __half2float(hw)));
}

// ---------------------------------------------------------------------------
// Merged transpose of Wq,Wk,Wv,Wo -> g_WqkvT / g_WoT fp16 [N,K] (K=DMODEL)
// ---------------------------------------------------------------------------
__global__ __launch_bounds__(256) void split_trA(const float* __restrict__ Wq,
                                                 const float* __restrict__ Wk,
                                                 const float* __restrict__ Wv,
                                                 const float* __restrict__ Wo,
                                                 __half* __restrict__ qkvT,
                                                 __half* __restrict__ woT)
{
    const int bx = blockIdx.x;
    const float* W; int N, n0; __half* dst; int dro;
    if (bx < 64)      { W = Wq; N = DMODEL; n0 = bx * 32;        dst = qkvT; dro = 0; }
    else if (bx < 80) { W = Wk; N = KV_DIM; n0 = (bx - 64) * 32; dst = qkvT; dro = DMODEL; }
    else if (bx < 96) { W = Wv; N = KV_DIM; n0 = (bx - 80) * 32; dst = qkvT; dro = DMODEL + KV_DIM; }
    else              { W = Wo; N = DMODEL; n0 = (bx - 96) * 32; dst = woT;  dro = 0; }

    __shared__ float s[32][33];
    int k0 = blockIdx.y * 32;
    int tx = threadIdx.x & 31, ty = threadIdx.x >> 5;
    #pragma unroll
    for (int j = 0; j < 4; j++)
        s[ty + j * 8][tx] = W[(size_t)(k0 + ty + j * 8) * N + n0 + tx];
    __syncthreads();
    #pragma unroll
    for (int j = 0; j < 4; j++) {
        int nn = ty + j * 8;
        dst[(size_t)(dro + n0 + nn) * DMODEL + k0 + tx] = __float2half(s[tx][nn]);
    }
}

// ---------------------------------------------------------------------------
// mma.sync fp16x2 GEMM (R13/R16-proven): C = (Ahi+Alo) @ (B[N,K])^T, fp32 out.
// CTA 128x128, BK=32, 8 warps, 3-stage cp.async pipeline, 2 CTA/SM.
// ---------------------------------------------------------------------------
#define GS_TILE   8192
#define GS_STAGE  24576
#define GEMM_SMEM 73728

__global__ __launch_bounds__(256, 2) void gemm_mma(
    const __half* __restrict__ Ahi, const __half* __restrict__ Alo,
    const __half* __restrict__ B,
    float* __restrict__ C, int M, int N, int K)
{
    extern __shared__ char dsm[];
    const uint32_t sbase = smem_u32(dsm);

    const int tid  = threadIdx.x;
    const int lane = tid & 31;
    const int w    = tid >> 5;
    const int wm   = w >> 2;
    const int wn   = w & 3;
    const int n0 = blockIdx.x * 128, m0 = blockIdx.y * 128;

    const __half* srcs[3] = {
        Ahi + (size_t)m0 * K, Alo + (size_t)m0 * K, B + (size_t)n0 * K };

    auto load_stage = [&](int stg, int kk) {
        uint32_t sb = sbase + stg * GS_STAGE;
        #pragma unroll
        for (int it = 0; it < 6; it++) {
            int idx  = it * 256 + tid;
            int tile = idx / 512;
            int rem  = idx & 511;
            int r    = rem >> 2;
            int c    = rem & 3;
            cp_async16(sb + tile * GS_TILE + swz64(r * 64 + c * 16),
                       srcs[tile] + (size_t)r * K + kk + c * 8);
        }
        CP_COMMIT();
    };

    float acc[4][4][4];
    #pragma unroll
    for (int i = 0; i < 4; i++)
        #pragma unroll
        for (int j = 0; j < 4; j++)
            #pragma unroll
            for (int q = 0; q < 4; q++) acc[i][j][q] = 0.f;

    const int ns = K >> 5;
    load_stage(0, 0);
    load_stage(1, 32);

    const uint32_t ldr = (lane & 15);
    const uint32_t ldc = (lane >> 4) * 16;

    for (int i = 0; i < ns; i++) {
        if (i + 1 < ns) { CP_WAIT(1); }
        else            { CP_WAIT(0); }
        __syncthreads();
        if (i + 2 < ns) load_stage((i + 2) % 3, (i + 2) * 32);

        const uint32_t sA = sbase + (i % 3) * GS_STAGE;
        const uint32_t sB = sA + 2 * GS_TILE;

        #pragma unroll
        for (int ks = 0; ks < 2; ks++) {
            const uint32_t kboff = ks * 32 + ldc;
            uint32_t af[2][4][4];
            #pragma unroll
            for (int p = 0; p < 2; p++)
                #pragma unroll
                for (int mt = 0; mt < 4; mt++)
                    ldm_x4(af[p][mt][0], af[p][mt][1], af[p][mt][2], af[p][mt][3],
                           sA + p * GS_TILE +
                           swz64((wm * 64 + mt * 16 + ldr) * 64 + kboff));

            #pragma unroll
            for (int nh = 0; nh < 2; nh++) {
                uint32_t bfr[4];
                ldm_x4(bfr[0], bfr[1], bfr[2], bfr[3],
                       sB + swz64((wn * 32 + nh * 16 + ldr) * 64 + kboff));

                #pragma unroll
                for (int mt = 0; mt < 4; mt++)
                    #pragma unroll
                    for (int sub = 0; sub < 2; sub++) {
                        float* d = acc[mt][nh * 2 + sub];
                        mma_f16(d[0], d[1], d[2], d[3],
                                af[0][mt][0], af[0][mt][1], af[0][mt][2], af[0][mt][3],
                                bfr[sub], bfr[sub + 2]);
                    }
                #pragma unroll
                for (int mt = 0; mt < 4; mt++)
                    #pragma unroll
                    for (int sub = 0; sub < 2; sub++) {
                        float* d = acc[mt][nh * 2 + sub];
                        mma_f16(d[0], d[1], d[2], d[3],
                                af[1][mt][0], af[1][mt][1], af[1][mt][2], af[1][mt][3],
                                bfr[sub], bfr[sub + 2]);
                    }
            }
        }
    }

    const int trow = lane >> 2;
    const int tcol = (lane & 3) * 2;
    #pragma unroll
    for (int mt = 0; mt < 4; mt++) {
        #pragma unroll
        for (int nt = 0; nt < 4; nt++) {
            const int rr = m0 + wm * 64 + mt * 16 + trow;
            const int cc = n0 + wn * 32 + nt * 8 + tcol;
            *(float2*)&C[(size_t)rr * N + cc] =
                make_float2(acc[mt][nt][0], acc[mt][nt][1]);
            *(float2*)&C[(size_t)(rr + 8) * N + cc] =
                make_float2(acc[mt][nt][2], acc[mt][nt][3]);
        }
    }
}

// ---------------------------------------------------------------------------
// Single-plane GEMM (Wo projection): C = Ah @ (B[N,K])^T, fp32 out.
// Same structure as gemm_mma, A truncated to one fp16 plane.
// ---------------------------------------------------------------------------
#define G1_STAGE  16384              // 2 tiles
#define GEMM1_SMEM 49152             // 3 stages

__global__ __launch_bounds__(256, 2) void gemm_mma1(
    const __half* __restrict__ Ah, const __half* __restrict__ B,
    float* __restrict__ C, int M, int N, int K)
{
    extern __shared__ char dsm[];
    const uint32_t sbase = smem_u32(dsm);

    const int tid  = threadIdx.x;
    const int lane = tid & 31;
    const int w    = tid >> 5;
    const int wm   = w >> 2;
    const int wn   = w & 3;
    const int n0 = blockIdx.x * 128, m0 = blockIdx.y * 128;

    const __half* srcs[2] = { Ah + (size_t)m0 * K, B + (size_t)n0 * K };

    auto load_stage = [&](int stg, int kk) {
        uint32_t sb = sbase + stg * G1_STAGE;
        #pragma unroll
        for (int it = 0; it < 4; it++) {
            int idx  = it * 256 + tid;
            int tile = idx >> 9;
            int rem  = idx & 511;
            int r    = rem >> 2;
            int c    = rem & 3;
            cp_async16(sb + tile * GS_TILE + swz64(r * 64 + c * 16),
                       srcs[tile] + (size_t)r * K + kk + c * 8);
        }
        CP_COMMIT();
    };

    float acc[4][4][4];
    #pragma unroll
    for (int i = 0; i < 4; i++)
        #pragma unroll
        for (int j = 0; j < 4; j++)
            #pragma unroll
            for (int q = 0; q < 4; q++) acc[i][j][q] = 0.f;

    const int ns = K >> 5;
    load_stage(0, 0);
    load_stage(1, 32);

    const uint32_t ldr = (lane & 15);
    const uint32_t ldc = (lane >> 4) * 16;

    for (int i = 0; i < ns; i++) {
        if (i + 1 < ns) { CP_WAIT(1); }
        else            { CP_WAIT(0); }
        __syncthreads();
        if (i + 2 < ns) load_stage((i + 2) % 3, (i + 2) * 32);

        const uint32_t sA = sbase + (i % 3) * G1_STAGE;
        const uint32_t sB = sA + GS_TILE;

        #pragma unroll
        for (int ks = 0; ks < 2; ks++) {
            const uint32_t kboff = ks * 32 + ldc;
            uint32_t af[4][4];
            #pragma unroll
            for (int mt = 0; mt < 4; mt++)
                ldm_x4(af[mt][0], af[mt][1], af[mt][2], af[mt][3],
                       sA + swz64((wm * 64 + mt * 16 + ldr) * 64 + kboff));

            #pragma unroll
            for (int nh = 0; nh < 2; nh++) {
                uint32_t bfr[4];
                ldm_x4(bfr[0], bfr[1], bfr[2], bfr[3],
                       sB + swz64((wn * 32 + nh * 16 + ldr) * 64 + kboff));

                #pragma unroll
                for (int mt = 0; mt < 4; mt++)
                    #pragma unroll
                    for (int sub = 0; sub < 2; sub++) {
                        float* d = acc[mt][nh * 2 + sub];
                        mma_f16(d[0], d[1], d[2], d[3],
                                af[mt][0], af[mt][1], af[mt][2], af[mt][3],
                                bfr[sub], bfr[sub + 2]);
                    }
            }
        }
    }

    const int trow = lane >> 2;
    const int tcol = (lane & 3) * 2;
    #pragma unroll
    for (int mt = 0; mt < 4; mt++) {
        #pragma unroll
        for (int nt = 0; nt < 4; nt++) {
            const int rr = m0 + wm * 64 + mt * 16 + trow;
            const int cc = n0 + wn * 32 + nt * 8 + tcol;
            *(float2*)&C[(size_t)rr * N + cc] =
                make_float2(acc[mt][nt][0], acc[mt][nt][1]);
            *(float2*)&C[(size_t)(rr + 8) * N + cc] =
                make_float2(acc[mt][nt][2], acc[mt][nt][3]);
        }
    }
}

// ---------------------------------------------------------------------------
// RoPE + split from fused g_QKV (R14/R16-proven)
// ---------------------------------------------------------------------------
__global__ void rope_split2(const float* __restrict__ cosp,
                            const float* __restrict__ sinp)
{
    const int per_s = (NH + 2 * NKV) * 64;
    int idx = blockIdx.x * blockDim.x + threadIdx.x;
    if (idx >= S_LEN * per_s) return;
    int s = idx / per_s;
    int r = idx % per_s;
    int hh = r >> 6;
    int d = r & 63;

    const float* row = g_QKV + (size_t)s * NQKV;

    if (hh < NH) {
        const float* p = row + hh * HD;
        size_t off = (size_t)s * DMODEL + hh * HD;
        float c0 = cosp[s * HD + d],      s0 = sinp[s * HD + d];
        float c1 = cosp[s * HD + d + 64], s1 = sinp[s * HD + d + 64];
        float x0 = p[d], x1 = p[d + 64];
        float y0 = x0 * c0 - x1 * s0;
        float y1 = x1 * c1 + x0 * s1;
        __half h0 = __float2half(y0), h1 = __float2half(y1);
        g_Qhi[off + d] = h0;      g_Qlo[off + d] = __float2half(y0 - __half2float(h0));
        g_Qhi[off + d + 64] = h1; g_Qlo[off + d + 64] = __float2half(y1 - __half2float(h1));
    } else if (hh < NH + NKV) {
        int kh2 = hh - NH;
        const float* p = row + DMODEL + kh2 * HD;
        size_t off = (size_t)s * KV_DIM + kh2 * HD;
        float c0 = cosp[s * HD + d],      s0 = sinp[s * HD + d];
        float c1 = cosp[s * HD + d + 64], s1 = sinp[s * HD + d + 64];
        float x0 = p[d], x1 = p[d + 64];
        g_Kh[off + d]      = __float2half(x0 * c0 - x1 * s0);
        g_Kh[off + d + 64] = __float2half(x1 * c1 + x0 * s1);
    } else {
        int vh2 = hh - NH - NKV;
        const float* p = row + DMODEL + KV_DIM + vh2 * HD;
        size_t off = (size_t)s * KV_DIM + vh2 * HD;
        g_Vh[off + d]      = __float2half(p[d]);
        g_Vh[off + d + 64] = __float2half(p[d + 64]);
    }
}

// ---------------------------------------------------------------------------
// Tensor-core flash attention v5 (R14/R16-proven): fp16x2, fp32 softmax/accum,
// CTA 64 q-rows x 1 head, 128 threads, BN=64, 3-stage KV pipeline, 2 CTA/SM.
// ---------------------------------------------------------------------------
#define FS_STRIDE   272
#define FKV_PLANE   (64 * FS_STRIDE)    // 17408
#define FS_STAGE    (2 * FKV_PLANE)     // 34816: Kh, Vh
#define FLASH_SMEM  (3 * FS_STAGE)      // 104448 -> 2 CTA/SM

__global__ __launch_bounds__(128, 2) void flash_mma()
{
    extern __shared__ char dsm[];
    const uint32_t sS = smem_u32(dsm);

    const int tid = threadIdx.x, lane = tid & 31, w = tid >> 5;
    const int qb = gridDim.x - 1 - blockIdx.x;
    const int h  = blockIdx.y;
    const int kvh = h >> 2;
    const int q0 = qb * 64;
    const float scale = 0.08838834764831845f;

    const uint32_t ldrow = lane & 15;
    const uint32_t ldoff = (lane >> 4) * 16;

    uint32_t qf[8][2][4];
    {
        const __half* qsrc[2] = { g_Qhi, g_Qlo };
        #pragma unroll
        for (int it = 0; it < 16; it++) {
            int idx = it * 128 + tid;
            int pl = idx >> 10, rem = idx & 1023;
            int r = rem >> 4, c = rem & 15;
            cp_async16(sS + pl * FKV_PLANE + r * FS_STRIDE + c * 16,
                       qsrc[pl] + (size_t)(q0 + r) * DMODEL + h * HD + c * 8);
        }
        CP_COMMIT();
        CP_WAIT(0);
        __syncthreads();
        #pragma unroll
        for (int kt = 0; kt < 8; kt++) {
            uint32_t qaddr = sS + (w * 16 + ldrow) * FS_STRIDE + kt * 32 + ldoff;
            ldm_x4(qf[kt][0][0], qf[kt][0][1], qf[kt][0][2], qf[kt][0][3], qaddr);
            ldm_x4(qf[kt][1][0], qf[kt][1][1], qf[kt][1][2], qf[kt][1][3],
                   qaddr + FKV_PLANE);
        }
        __syncthreads();
    }

    auto load_stage = [&](int stg, int k0) {
        const __half* src[2] = { g_Kh, g_Vh };
        uint32_t base = sS + stg * FS_STAGE;
        #pragma unroll
        for (int it = 0; it < 16; it++) {
            int idx = it * 128 + tid;
            int tile = idx >> 10, rem = idx & 1023;
            int r = rem >> 4, c = rem & 15;
            cp_async16(base + tile * FKV_PLANE + r * FS_STRIDE + c * 16,
                       src[tile] + (size_t)(k0 + r) * KV_DIM + kvh * HD + c * 8);
        }
        CP_COMMIT();
    };

    const int niter = qb + 1;
    load_stage(0, 0);
    if (niter > 1) load_stage(1, 64);

    float o[16][4];
    #pragma unroll
    for (int t = 0; t < 16; t++)
        #pragma unroll
        for (int e = 0; e < 4; e++) o[t][e] = 0.f;
    float m0 = -1e30f, m1 = -1e30f, l0 = 0.f, l1 = 0.f;

    const int rlow = q0 + w * 16 + (lane >> 2);

    for (int kb = 0; kb < niter; kb++) {
        if (kb + 1 < niter) { CP_WAIT(1); }
        else                { CP_WAIT(0); }
        __syncthreads();
        if (kb + 2 < niter) load_stage((kb + 2) % 3, (kb + 2) * 64);

        const uint32_t st = sS + (kb % 3) * FS_STAGE;

        float s_acc[8][4];
        #pragma unroll
        for (int t = 0; t < 8; t++)
            #pragma unroll
            for (int e = 0; e < 4; e++) s_acc[t][e] = 0.f;

        #pragma unroll
        for (int kt = 0; kt < 8; kt++) {
            uint32_t kh_[4][4];
            #pragma unroll
            for (int nt2 = 0; nt2 < 4; nt2++) {
                uint32_t kaddr = st + (nt2 * 16 + ldrow) * FS_STRIDE + kt * 32 + ldoff;
                ldm_x4(kh_[nt2][0], kh_[nt2][1], kh_[nt2][2], kh_[nt2][3], kaddr);
            }
            #pragma unroll
            for (int nt2 = 0; nt2 < 4; nt2++)
                #pragma unroll
                for (int sub = 0; sub < 2; sub++) {
                    float* d = s_acc[nt2 * 2 + sub];
                    mma_f16(d[0], d[1], d[2], d[3],
                            qf[kt][0][0], qf[kt][0][1], qf[kt][0][2], qf[kt][0][3],
                            kh_[nt2][sub], kh_[nt2][sub + 2]);
                }
            #pragma unroll
            for (int nt2 = 0; nt2 < 4; nt2++)
                #pragma unroll
                for (int sub = 0; sub < 2; sub++) {
                    float* d = s_acc[nt2 * 2 + sub];
                    mma_f16(d[0], d[1], d[2], d[3],
                            qf[kt][1][0], qf[kt][1][1], qf[kt][1][2], qf[kt][1][3],
                            kh_[nt2][sub], kh_[nt2][sub + 2]);
                }
        }

        const bool needmask = (kb == qb);
        const int colb = kb * 64 + (lane & 3) * 2;
        #pragma unroll
        for (int t = 0; t < 8; t++) {
            #pragma unroll
            for (int e = 0; e < 4; e++) {
                float v = s_acc[t][e] * scale;
                if (needmask) {
                    int col = colb + t * 8 + (e & 1);
                    int row = rlow + ((e >= 2) ? 8 : 0);
                    if (col > row) v = -1e30f;
                }
                s_acc[t][e] = v;
            }
        }

        float rmax0 = -1e30f, rmax1 = -1e30f;
        #pragma unroll
        for (int t = 0; t < 8; t++) {
            rmax0 = fmaxf(rmax0, fmaxf(s_acc[t][0], s_acc[t][1]));
            rmax1 = fmaxf(rmax1, fmaxf(s_acc[t][2], s_acc[t][3]));
        }
        #pragma unroll
        for (int off = 1; off <= 2; off <<= 1) {
            rmax0 = fmaxf(rmax0, __shfl_xor_sync(0xffffffffu, rmax0, off));
            rmax1 = fmaxf(rmax1, __shfl_xor_sync(0xffffffffu, rmax1, off));
        }
        float mn0 = fmaxf(m0, rmax0), mn1 = fmaxf(m1, rmax1);
        float al0 = __expf(m0 - mn0), al1 = __expf(m1 - mn1);
        float sum0 = 0.f, sum1 = 0.f;
        #pragma unroll
        for (int t = 0; t < 8; t++) {
            float p0 = __expf(s_acc[t][0] - mn0);
            float p1 = __expf(s_acc[t][1] - mn0);
            float p2 = __expf(s_acc[t][2] - mn1);
            float p3 = __expf(s_acc[t][3] - mn1);
            s_acc[t][0] = p0; s_acc[t][1] = p1; s_acc[t][2] = p2; s_acc[t][3] = p3;
            sum0 += p0 + p1; sum1 += p2 + p3;
        }
        #pragma unroll
        for (int off = 1; off <= 2; off <<= 1) {
            sum0 += __shfl_xor_sync(0xffffffffu, sum0, off);
            sum1 += __shfl_xor_sync(0xffffffffu, sum1, off);
        }
        l0 = l0 * al0 + sum0;  m0 = mn0;
        l1 = l1 * al1 + sum1;  m1 = mn1;
        #pragma unroll
        for (int t = 0; t < 16; t++) {
            o[t][0] *= al0; o[t][1] *= al0;
            o[t][2] *= al1; o[t][3] *= al1;
        }

        #pragma unroll
        for (int j = 0; j < 4; j++) {
            float lx[8];
            uint32_t ah[4], alr[4];
            ah[0] = pack_hi(s_acc[2*j][0],   s_acc[2*j][1],   lx[0], lx[1]);
            ah[1] = pack_hi(s_acc[2*j][2],   s_acc[2*j][3],   lx[2], lx[3]);
            ah[2] = pack_hi(s_acc[2*j+1][0], s_acc[2*j+1][1], lx[4], lx[5]);
            ah[3] = pack_hi(s_acc[2*j+1][2], s_acc[2*j+1][3], lx[6], lx[7]);
            alr[0] = pack_h(lx[0], lx[1]);
            alr[1] = pack_h(lx[2], lx[3]);
            alr[2] = pack_h(lx[4], lx[5]);
            alr[3] = pack_h(lx[6], lx[7]);

            #pragma unroll
            for (int g = 0; g < 2; g++) {
                uint32_t vh4[4][4];
                #pragma unroll
                for (int q4 = 0; q4 < 4; q4++) {
                    int dt2 = g * 4 + q4;
                    uint32_t vaddr = st + FKV_PLANE +
                                     (j * 16 + ldrow) * FS_STRIDE + dt2 * 32 + ldoff;
                    ldm_x4_t(vh4[q4][0], vh4[q4][1], vh4[q4][2], vh4[q4][3], vaddr);
                }
                #pragma unroll
                for (int q4 = 0; q4 < 4; q4++)
                    #pragma unroll
                    for (int sub = 0; sub < 2; sub++) {
                        float* d = o[(g * 4 + q4) * 2 + sub];
                        mma_f16(d[0], d[1], d[2], d[3],
                                ah[0], ah[1], ah[2], ah[3],
                                vh4[q4][2*sub], vh4[q4][2*sub+1]);
                    }
                #pragma unroll
                for (int q4 = 0; q4 < 4; q4++)
                    #pragma unroll
                    for (int sub = 0; sub < 2; sub++) {
                        float* d = o[(g * 4 + q4) * 2 + sub];
                        mma_f16(d[0], d[1], d[2], d[3],
                                alr[0], alr[1], alr[2], alr[3],
                                vh4[q4][2*sub], vh4[q4][2*sub+1]);
                    }
            }
        }
    }

    float inv0 = 1.0f / l0, inv1 = 1.0f / l1;
    const int row0 = q0 + w * 16 + (lane >> 2);
    #pragma unroll
    for (int t = 0; t < 16; t++) {
        int d = t * 8 + (lane & 3) * 2;
        size_t off0 = (size_t)row0 * DMODEL + h * HD + d;
        size_t off1 = off0 + 8 * DMODEL;
        float v0 = o[t][0] * inv0, v1 = o[t][1] * inv0;
        float v2 = o[t][2] * inv1, v3 = o[t][3] * inv1;
        __half h0 = __float2half(v0), h1 = __float2half(v1);
        __half h2 = __float2half(v2), h3 = __float2half(v3);
        *(__half2*)&g_Ohi[off0] = __halves2half2(h0, h1);
        *(__half2*)&g_Ohi[off1] = __halves2half2(h2, h3);
        *(__half2*)&g_Olo[off0] = __halves2half2(
            __float2half(v0 - __half2float(h0)),
            __float2half(v1 - __half2float(h1)));
        *(__half2*)&g_Olo[off1] = __halves2half2(
            __float2half(v2 - __half2float(h2)),
            __float2half(v3 - __half2float(h3)));
    }
}

// ---------------------------------------------------------------------------
extern "C" void kernel_launch(void* const* d_in, const int* in_sizes, int n_in,
                              void* d_out, int out_size)
{
    const float* X    = (const float*)d_in[0];
    const float* cosp = (const float*)d_in[1];
    const float* sinp = (const float*)d_in[2];
    const float* Wq   = (const float*)d_in[3];
    const float* Wk   = (const float*)d_in[4];
    const float* Wv   = (const float*)d_in[5];
    const float* Wo   = (const float*)d_in[6];
    float* out = (float*)d_out;

    float* gqkv;
    cudaGetSymbolAddress((void**)&gqkv, g_QKV);
    __half *xh, *xl, *oh, *qkvw, *wow;
    cudaGetSymbolAddress((void**)&xh, g_Xhi);   cudaGetSymbolAddress((void**)&xl, g_Xlo);
    cudaGetSymbolAddress((void**)&oh, g_Ohi);
    cudaGetSymbolAddress((void**)&qkvw, g_WqkvT);
    cudaGetSymbolAddress((void**)&wow, g_WoT);

    cudaFuncSetAttribute(gemm_mma, cudaFuncAttributeMaxDynamicSharedMemorySize, GEMM_SMEM);
    cudaFuncSetAttribute(gemm_mma1, cudaFuncAttributeMaxDynamicSharedMemorySize, GEMM1_SMEM);
    cudaFuncSetAttribute(flash_mma, cudaFuncAttributeMaxDynamicSharedMemorySize, FLASH_SMEM);

    // #1 split X -> fp16 hi/lo (vectorized)
    int n4 = S_LEN * DMODEL / 4;
    split_rm4<<<(n4 + 255) / 256, 256>>>((const float4*)X, (__half2*)xh,
                                         (__half2*)xl, n4);
    // #2 merged transpose Wq/Wk/Wv/Wo
    split_trA<<<dim3(160, 64), 256>>>(Wq, Wk, Wv, Wo, qkvw, wow);
    // #3 fused QKV projection (2-term)
    gemm_mma<<<dim3(NQKV / 128, S_LEN / 128), 256, GEMM_SMEM>>>(
        xh, xl, qkvw, gqkv, S_LEN, NQKV, DMODEL);
    // #4 RoPE(Q,K) + V -> fp16 planes
    int rthreads = S_LEN * (NH + 2 * NKV) * 64;
    rope_split2<<<(rthreads + 255) / 256, 256>>>(cosp, sinp);
    // #5 flash attention v5 (BN=64)
    flash_mma<<<dim3(S_LEN / 64, NH), 128, FLASH_SMEM>>>();
    // #6 output projection (1-term: O-hi only)
    gemm_mma1<<<dim3(DMODEL / 128, S_LEN / 128), 256, GEMM1_SMEM>>>(
        oh, wow, out, S_LEN, DMODEL, DMODEL);
}